// round 3
// baseline (speedup 1.0000x reference)
#include <cuda_runtime.h>
#include <stdint.h>

#define BATCH 2048
#define EPS 1e-5f

// ---------------- static scratch ----------------
__device__ uint32_t           g_h1[BATCH * 28 * 28];    // stem out, 32 ch packed
__device__ unsigned long long g_h2[BATCH * 14 * 14];    // block1 out, 64 ch packed
__device__ uint32_t           g_h3u[BATCH * 49 * 2];    // block2 out, 2x u32 halves
__device__ uint32_t           g_w2p[64 * 9];
__device__ unsigned long long g_w3p[64 * 9];
__device__ unsigned long long g_wfcp[256 * 49];
__device__ float g_inv1[32], g_inv2[64], g_inv3[64], g_inv4[256];
// border-correction tables: R[c][4], C[c][4], T[c][16] (index 3 = sentinel zero)
__device__ int g_R2[64 * 4], g_C2[64 * 4], g_T2[64 * 16];
__device__ int g_R3[64 * 4], g_C3[64 * 4], g_T3[64 * 16];

// ---------------- packing + BN + border tables ----------------
__global__ void pack_kernel(const float* __restrict__ w2, const float* __restrict__ w3,
                            const float* __restrict__ wfc,
                            const float* __restrict__ g1, const float* __restrict__ v1,
                            const float* __restrict__ g2, const float* __restrict__ v2,
                            const float* __restrict__ g3, const float* __restrict__ v3,
                            const float* __restrict__ g4, const float* __restrict__ v4) {
    int idx = blockIdx.x * 256 + threadIdx.x;
    if (idx < 576) {                                   // w2: [64,32,3,3]
        int o = idx / 9, t = idx % 9;
        uint32_t bits = 0;
        for (int c = 0; c < 32; c++)
            bits |= (w2[o * 288 + c * 9 + t] >= 0.f ? 1u : 0u) << c;
        g_w2p[idx] = bits;
    } else if (idx < 1152) {                           // w3: [64,64,3,3]
        int j = idx - 576; int o = j / 9, t = j % 9;
        unsigned long long bits = 0;
        for (int c = 0; c < 64; c++)
            bits |= (unsigned long long)(w3[o * 576 + c * 9 + t] >= 0.f) << c;
        g_w3p[j] = bits;
    } else if (idx < 13696) {                          // w_fc: [256,3136]
        int j = idx - 1152; int o = j / 49, p = j % 49;
        unsigned long long bits = 0;
        for (int c = 0; c < 64; c++)
            bits |= (unsigned long long)(wfc[o * 3136 + c * 49 + p] >= 0.f) << c;
        g_wfcp[j] = bits;
    } else if (idx < 13728) {
        int c = idx - 13696; g_inv1[c] = g1[c] / sqrtf(v1[c] + EPS);
    } else if (idx < 13792) {
        int c = idx - 13728; g_inv2[c] = g2[c] / sqrtf(v2[c] + EPS);
    } else if (idx < 13856) {
        int c = idx - 13792; g_inv3[c] = g3[c] / sqrtf(v3[c] + EPS);
    } else if (idx < 14112) {
        int c = idx - 13856; g_inv4[c] = g4[c] / sqrtf(v4[c] + EPS);
    } else if (idx < 14176) {                          // conv2 correction tables
        int c = idx - 14112;
        int tp[9];
        for (int t = 0; t < 9; t++) {
            uint32_t bits = 0;
            for (int ic = 0; ic < 32; ic++)
                bits |= (w2[c * 288 + ic * 9 + t] >= 0.f ? 1u : 0u) << ic;
            tp[t] = __popc(bits);
        }
        for (int r = 0; r < 4; r++) {
            g_R2[c * 4 + r] = (r < 3) ? tp[r * 3] + tp[r * 3 + 1] + tp[r * 3 + 2] : 0;
            g_C2[c * 4 + r] = (r < 3) ? tp[r] + tp[3 + r] + tp[6 + r] : 0;
        }
        for (int a = 0; a < 4; a++)
            for (int b = 0; b < 4; b++)
                g_T2[c * 16 + a * 4 + b] = (a < 3 && b < 3) ? tp[a * 3 + b] : 0;
    } else if (idx < 14240) {                          // conv3 correction tables
        int c = idx - 14176;
        int tp[9];
        for (int t = 0; t < 9; t++) {
            unsigned long long bits = 0;
            for (int ic = 0; ic < 64; ic++)
                bits |= (unsigned long long)(w3[c * 576 + ic * 9 + t] >= 0.f) << ic;
            tp[t] = __popcll(bits);
        }
        for (int r = 0; r < 4; r++) {
            g_R3[c * 4 + r] = (r < 3) ? tp[r * 3] + tp[r * 3 + 1] + tp[r * 3 + 2] : 0;
            g_C3[c * 4 + r] = (r < 3) ? tp[r] + tp[3 + r] + tp[6 + r] : 0;
        }
        for (int a = 0; a < 4; a++)
            for (int b = 0; b < 4; b++)
                g_T3[c * 16 + a * 4 + b] = (a < 3 && b < 3) ? tp[a * 3 + b] : 0;
    }
}

// ---------------- stem: fp32 conv3x3(1->32) + BN + sign ----------------
__global__ void __launch_bounds__(256) stem_kernel(const float* __restrict__ x,
                                                   const float* __restrict__ ws,
                                                   const float* __restrict__ m1,
                                                   const float* __restrict__ b1) {
    __shared__ float sw[288], sinv[32], sm[32], sb[32];
    int t = threadIdx.x;
    for (int i = t; i < 288; i += 256) sw[i] = ws[i];
    if (t < 32) { sinv[t] = g_inv1[t]; sm[t] = m1[t]; sb[t] = b1[t]; }
    __syncthreads();

    int idx = blockIdx.x * 256 + t;
    int b = idx / 784, p = idx % 784;
    int y = p / 28, xx = p % 28;
    const float* xb = x + b * 784;

    float win[9];
#pragma unroll
    for (int dy = 0; dy < 3; dy++)
#pragma unroll
        for (int dx = 0; dx < 3; dx++) {
            int yy = y + dy - 1, xc = xx + dx - 1;
            win[dy * 3 + dx] = (yy >= 0 && yy < 28 && xc >= 0 && xc < 28) ? xb[yy * 28 + xc] : 0.f;
        }

    uint32_t bits = 0;
#pragma unroll 4
    for (int c = 0; c < 32; c++) {
        float s = 0.f;
#pragma unroll
        for (int k = 0; k < 9; k++) s += sw[c * 9 + k] * win[k];
        float v = (s - sm[c]) * sinv[c] + sb[c];
        bits |= (v >= 0.f ? 1u : 0u) << c;
    }
    g_h1[idx] = bits;
}

// ---------------- block1: binary conv(32->64) + BN + pool + sign ----------------
__global__ void __launch_bounds__(256) conv2_kernel(const float* __restrict__ m2,
                                                    const float* __restrict__ b2) {
    __shared__ uint32_t swt[576];
    __shared__ int sR[256], sC[256], sT[1024];
    __shared__ float sinv[64], smn[64], sbt[64];
    int t = threadIdx.x;
    for (int i = t; i < 576; i += 256) swt[i] = g_w2p[i];
    if (t < 256) { sR[t] = g_R2[t]; sC[t] = g_C2[t]; }
    for (int i = t; i < 1024; i += 256) sT[i] = g_T2[i];
    if (t < 64) { sinv[t] = g_inv2[t]; smn[t] = m2[t]; sbt[t] = b2[t]; }
    __syncthreads();

    int idx = blockIdx.x * 256 + t;                 // 2048*196 threads
    int b = idx / 196, p = idx % 196;
    int oy = p / 14, ox = p % 14;
    const uint32_t* h = g_h1 + b * 784;

    int rbase = 2 * oy - 1, cbase = 2 * ox - 1;
    bool rv0 = oy > 0, rv3 = oy < 13, cv0 = ox > 0, cv3 = ox < 13;

    uint32_t win[16];
#pragma unroll
    for (int i = 0; i < 4; i++) {
        bool rok = (i == 0) ? rv0 : (i == 3 ? rv3 : true);
#pragma unroll
        for (int j = 0; j < 4; j++) {
            bool cok = (j == 0) ? cv0 : (j == 3 ? cv3 : true);
            win[i * 4 + j] = (rok && cok) ? h[(rbase + i) * 28 + (cbase + j)] : 0u;
        }
    }
    int a0 = rv0 ? 3 : 0, a1 = rv3 ? 3 : 2;
    int b0 = cv0 ? 3 : 0, b1 = cv3 ? 3 : 2;
    int vr0 = rv0 ? 3 : 2, vr1 = rv3 ? 3 : 2;
    int vc0 = cv0 ? 3 : 2, vc1 = cv3 ? 3 : 2;
    float base00 = 32.f * vr0 * vc0, base01 = 32.f * vr0 * vc1;
    float base10 = 32.f * vr1 * vc0, base11 = 32.f * vr1 * vc1;

    unsigned long long obits = 0;
    for (int c = 0; c < 64; c++) {
        uint32_t wt[9];
#pragma unroll
        for (int k = 0; k < 9; k++) wt[k] = swt[c * 9 + k];
        int acc[4] = {0, 0, 0, 0};
#pragma unroll
        for (int dy = 0; dy < 3; dy++)
#pragma unroll
            for (int dx = 0; dx < 3; dx++) {
                uint32_t w = wt[dy * 3 + dx];
                acc[0] += __popc(win[dy * 4 + dx] ^ w);
                acc[1] += __popc(win[dy * 4 + dx + 1] ^ w);
                acc[2] += __popc(win[(dy + 1) * 4 + dx] ^ w);
                acc[3] += __popc(win[(dy + 1) * 4 + dx + 1] ^ w);
            }
        int Ra = sR[c * 4 + a0], Rb = sR[c * 4 + a1];
        int Ca = sC[c * 4 + b0], Cb = sC[c * 4 + b1];
        const int* Tc = sT + c * 16;
        int c00 = Ra + Ca - Tc[a0 * 4 + b0];
        int c01 = Ra + Cb - Tc[a0 * 4 + b1];
        int c10 = Rb + Ca - Tc[a1 * 4 + b0];
        int c11 = Rb + Cb - Tc[a1 * 4 + b1];
        float inv = sinv[c], mm = smn[c], bb = sbt[c];
        float d00 = base00 - 2.f * (float)(acc[0] - c00);
        float d01 = base01 - 2.f * (float)(acc[1] - c01);
        float d10 = base10 - 2.f * (float)(acc[2] - c10);
        float d11 = base11 - 2.f * (float)(acc[3] - c11);
        float v0 = fmaxf((d00 - mm) * inv + bb, (d01 - mm) * inv + bb);
        float v1 = fmaxf((d10 - mm) * inv + bb, (d11 - mm) * inv + bb);
        obits |= (unsigned long long)(fmaxf(v0, v1) >= 0.f) << c;
    }
    g_h2[idx] = obits;
}

// ---------------- block2: binary conv(64->64), 32 ch per thread ----------------
__global__ void __launch_bounds__(256) conv3_kernel(const float* __restrict__ m3,
                                                    const float* __restrict__ b3) {
    __shared__ unsigned long long swt[576];
    __shared__ int sR[256], sC[256], sT[1024];
    __shared__ float sinv[64], smn[64], sbt[64];
    int t = threadIdx.x;
    for (int i = t; i < 576; i += 256) swt[i] = g_w3p[i];
    if (t < 256) { sR[t] = g_R3[t]; sC[t] = g_C3[t]; }
    for (int i = t; i < 1024; i += 256) sT[i] = g_T3[i];
    if (t < 64) { sinv[t] = g_inv3[t]; smn[t] = m3[t]; sbt[t] = b3[t]; }
    __syncthreads();

    int idx = blockIdx.x * 256 + t;                 // 2048*49*2 threads
    int cell = idx >> 1, half = idx & 1;
    int b = cell / 49, p = cell % 49;
    int oy = p / 7, ox = p % 7;
    const unsigned long long* h = g_h2 + b * 196;

    int rbase = 2 * oy - 1, cbase = 2 * ox - 1;
    bool rv0 = oy > 0, rv3 = oy < 6, cv0 = ox > 0, cv3 = ox < 6;

    unsigned long long win[16];
#pragma unroll
    for (int i = 0; i < 4; i++) {
        bool rok = (i == 0) ? rv0 : (i == 3 ? rv3 : true);
#pragma unroll
        for (int j = 0; j < 4; j++) {
            bool cok = (j == 0) ? cv0 : (j == 3 ? cv3 : true);
            win[i * 4 + j] = (rok && cok) ? h[(rbase + i) * 14 + (cbase + j)] : 0ull;
        }
    }
    int a0 = rv0 ? 3 : 0, a1 = rv3 ? 3 : 2;
    int b0 = cv0 ? 3 : 0, b1 = cv3 ? 3 : 2;
    int vr0 = rv0 ? 3 : 2, vr1 = rv3 ? 3 : 2;
    int vc0 = cv0 ? 3 : 2, vc1 = cv3 ? 3 : 2;
    float base00 = 64.f * vr0 * vc0, base01 = 64.f * vr0 * vc1;
    float base10 = 64.f * vr1 * vc0, base11 = 64.f * vr1 * vc1;

    int cbeg = half * 32;
    uint32_t obits = 0;
    for (int ci = 0; ci < 32; ci++) {
        int c = cbeg + ci;
        unsigned long long wt[9];
#pragma unroll
        for (int k = 0; k < 9; k++) wt[k] = swt[c * 9 + k];
        int acc[4] = {0, 0, 0, 0};
#pragma unroll
        for (int dy = 0; dy < 3; dy++)
#pragma unroll
            for (int dx = 0; dx < 3; dx++) {
                unsigned long long w = wt[dy * 3 + dx];
                acc[0] += __popcll(win[dy * 4 + dx] ^ w);
                acc[1] += __popcll(win[dy * 4 + dx + 1] ^ w);
                acc[2] += __popcll(win[(dy + 1) * 4 + dx] ^ w);
                acc[3] += __popcll(win[(dy + 1) * 4 + dx + 1] ^ w);
            }
        int Ra = sR[c * 4 + a0], Rb = sR[c * 4 + a1];
        int Ca = sC[c * 4 + b0], Cb = sC[c * 4 + b1];
        const int* Tc = sT + c * 16;
        int c00 = Ra + Ca - Tc[a0 * 4 + b0];
        int c01 = Ra + Cb - Tc[a0 * 4 + b1];
        int c10 = Rb + Ca - Tc[a1 * 4 + b0];
        int c11 = Rb + Cb - Tc[a1 * 4 + b1];
        float inv = sinv[c], mm = smn[c], bb = sbt[c];
        float d00 = base00 - 2.f * (float)(acc[0] - c00);
        float d01 = base01 - 2.f * (float)(acc[1] - c01);
        float d10 = base10 - 2.f * (float)(acc[2] - c10);
        float d11 = base11 - 2.f * (float)(acc[3] - c11);
        float v0 = fmaxf((d00 - mm) * inv + bb, (d01 - mm) * inv + bb);
        float v1 = fmaxf((d10 - mm) * inv + bb, (d11 - mm) * inv + bb);
        obits |= (uint32_t)(fmaxf(v0, v1) >= 0.f) << ci;
    }
    g_h3u[cell * 2 + half] = obits;
}

// ---------------- classifier ----------------
__global__ void __launch_bounds__(256) fc_kernel(const float* __restrict__ m4,
                                                 const float* __restrict__ b4,
                                                 const float* __restrict__ w_head,
                                                 const float* __restrict__ b_head,
                                                 float* __restrict__ out) {
    __shared__ unsigned long long xrow[49];
    __shared__ float h4[256];
    int b = blockIdx.x, t = threadIdx.x;
    if (t < 49) {
        uint32_t lo = g_h3u[(b * 49 + t) * 2];
        uint32_t hi = g_h3u[(b * 49 + t) * 2 + 1];
        xrow[t] = (unsigned long long)lo | ((unsigned long long)hi << 32);
    }
    __syncthreads();

    const unsigned long long* wr = g_wfcp + t * 49;
    int acc = 0;
#pragma unroll
    for (int p = 0; p < 49; p++) acc += __popcll(xrow[p] ^ wr[p]);
    float val = (float)(3136 - 2 * acc);
    h4[t] = (val - m4[t]) * g_inv4[t] + b4[t];
    __syncthreads();

    if (t < 10) {
        float s = b_head[t];
        const float* wh = w_head + t * 256;
#pragma unroll 8
        for (int c = 0; c < 256; c++) s += h4[c] * wh[c];
        out[b * 10 + t] = s;
    }
}

// ---------------- launch ----------------
extern "C" void kernel_launch(void* const* d_in, const int* in_sizes, int n_in,
                              void* d_out, int out_size) {
    const float* x      = (const float*)d_in[0];
    const float* w_stem = (const float*)d_in[1];
    const float* g1 = (const float*)d_in[2];
    const float* b1 = (const float*)d_in[3];
    const float* m1 = (const float*)d_in[4];
    const float* v1 = (const float*)d_in[5];
    const float* w2 = (const float*)d_in[6];
    const float* g2 = (const float*)d_in[7];
    const float* b2 = (const float*)d_in[8];
    const float* m2 = (const float*)d_in[9];
    const float* v2 = (const float*)d_in[10];
    const float* w3 = (const float*)d_in[11];
    const float* g3 = (const float*)d_in[12];
    const float* b3 = (const float*)d_in[13];
    const float* m3 = (const float*)d_in[14];
    const float* v3 = (const float*)d_in[15];
    const float* w_fc = (const float*)d_in[16];
    const float* g4 = (const float*)d_in[17];
    const float* b4 = (const float*)d_in[18];
    const float* m4 = (const float*)d_in[19];
    const float* v4 = (const float*)d_in[20];
    const float* w_head = (const float*)d_in[21];
    const float* b_head = (const float*)d_in[22];
    float* out = (float*)d_out;

    pack_kernel<<<56, 256>>>(w2, w3, w_fc, g1, v1, g2, v2, g3, v3, g4, v4);
    stem_kernel<<<(BATCH * 784) / 256, 256>>>(x, w_stem, m1, b1);
    conv2_kernel<<<(BATCH * 196) / 256, 256>>>(m2, b2);
    conv3_kernel<<<(BATCH * 49 * 2) / 256, 256>>>(m3, b3);
    fc_kernel<<<BATCH, 256>>>(m4, b4, w_head, b_head, out);
}

// round 4
// speedup vs baseline: 1.0957x; 1.0957x over previous
#include <cuda_runtime.h>
#include <stdint.h>

#define BATCH 2048
#define EPS 1e-5f

// ---------------- static scratch ----------------
__device__ uint32_t           g_h1[BATCH * 784];        // stem out, 32 ch packed (written as u16 halves)
__device__ unsigned long long g_h2[BATCH * 196];        // block1 out, 64 ch packed (written as u32 halves)
__device__ uint32_t           g_h3u[BATCH * 49 * 2];    // block2 out, 2x u32 halves
__device__ uint32_t           g_w2p[64 * 12];           // sign(w2) packed, stride 12 (uint4-loadable)
__device__ unsigned long long g_w3p[64 * 10];           // sign(w3) packed, stride 10 (ulonglong2-loadable)
__device__ unsigned long long g_wfcp[256 * 49];         // sign(w_fc) packed
__device__ float4 g_bn1[32], g_bn2[64], g_bn3[64], g_bn4[256];  // (inv, mean, beta, 0)

// ---------------- packing + BN precompute ----------------
__global__ void pack_kernel(const float* __restrict__ w2, const float* __restrict__ w3,
                            const float* __restrict__ wfc,
                            const float* __restrict__ g1, const float* __restrict__ v1,
                            const float* __restrict__ m1, const float* __restrict__ b1,
                            const float* __restrict__ g2, const float* __restrict__ v2,
                            const float* __restrict__ m2, const float* __restrict__ b2,
                            const float* __restrict__ g3, const float* __restrict__ v3,
                            const float* __restrict__ m3, const float* __restrict__ b3,
                            const float* __restrict__ g4, const float* __restrict__ v4,
                            const float* __restrict__ m4, const float* __restrict__ b4) {
    int idx = blockIdx.x * 256 + threadIdx.x;
    if (idx < 768) {                                   // w2: [64,32,3,3] -> stride 12
        int o = idx / 12, t = idx % 12;
        uint32_t bits = 0;
        if (t < 9)
            for (int c = 0; c < 32; c++)
                bits |= (w2[o * 288 + c * 9 + t] >= 0.f ? 1u : 0u) << c;
        g_w2p[idx] = bits;
    } else if (idx < 1408) {                           // w3: [64,64,3,3] -> stride 10
        int j = idx - 768; int o = j / 10, t = j % 10;
        unsigned long long bits = 0;
        if (t < 9)
            for (int c = 0; c < 64; c++)
                bits |= (unsigned long long)(w3[o * 576 + c * 9 + t] >= 0.f) << c;
        g_w3p[j] = bits;
    } else if (idx < 13952) {                          // w_fc: [256,3136]
        int j = idx - 1408; int o = j / 49, p = j % 49;
        unsigned long long bits = 0;
        for (int c = 0; c < 64; c++)
            bits |= (unsigned long long)(wfc[o * 3136 + c * 49 + p] >= 0.f) << c;
        g_wfcp[j] = bits;
    } else if (idx < 13984) {
        int c = idx - 13952;
        g_bn1[c] = make_float4(g1[c] / sqrtf(v1[c] + EPS), m1[c], b1[c], 0.f);
    } else if (idx < 14048) {
        int c = idx - 13984;
        g_bn2[c] = make_float4(g2[c] / sqrtf(v2[c] + EPS), m2[c], b2[c], 0.f);
    } else if (idx < 14112) {
        int c = idx - 14048;
        g_bn3[c] = make_float4(g3[c] / sqrtf(v3[c] + EPS), m3[c], b3[c], 0.f);
    } else if (idx < 14368) {
        int c = idx - 14112;
        g_bn4[c] = make_float4(g4[c] / sqrtf(v4[c] + EPS), m4[c], b4[c], 0.f);
    }
}

// ---------------- stem: fp32 conv3x3(1->32) + BN + sign, 16 ch/thread ----------------
__global__ void __launch_bounds__(256) stem_kernel(const float* __restrict__ x,
                                                   const float* __restrict__ ws) {
    __shared__ float sw[288];
    __shared__ float4 sbn[32];
    int t = threadIdx.x;
    for (int i = t; i < 288; i += 256) sw[i] = ws[i];
    if (t < 32) sbn[t] = g_bn1[t];
    __syncthreads();

    int idx = blockIdx.x * 256 + t;               // 2048*784*2 threads
    int pix = idx >> 1, half = idx & 1;
    int b = pix / 784, p = pix % 784;
    int y = p / 28, xx = p % 28;
    const float* xb = x + b * 784;

    float win[9];
#pragma unroll
    for (int dy = 0; dy < 3; dy++)
#pragma unroll
        for (int dx = 0; dx < 3; dx++) {
            int yy = y + dy - 1, xc = xx + dx - 1;
            win[dy * 3 + dx] = (yy >= 0 && yy < 28 && xc >= 0 && xc < 28) ? xb[yy * 28 + xc] : 0.f;
        }

    int cb = half * 16;
    uint32_t bits = 0;
#pragma unroll
    for (int ci = 0; ci < 16; ci++) {
        int c = cb + ci;
        float s = 0.f;
#pragma unroll
        for (int k = 0; k < 9; k++) s += sw[c * 9 + k] * win[k];
        float4 bn = sbn[c];
        float v = (s - bn.y) * bn.x + bn.z;
        bits |= (v >= 0.f ? 1u : 0u) << ci;
    }
    ((uint16_t*)g_h1)[pix * 2 + half] = (uint16_t)bits;
}

// ---------------- block1: binary conv(32->64) + BN + pool + sign, 32 ch/thread ----------------
__global__ void __launch_bounds__(256) conv2_kernel() {
    __shared__ __align__(16) uint32_t swt[768];
    __shared__ float4 sbn[64];
    int t = threadIdx.x;
    for (int i = t; i < 768; i += 256) swt[i] = g_w2p[i];
    if (t < 64) sbn[t] = g_bn2[t];
    __syncthreads();

    int idx = blockIdx.x * 256 + t;                 // 2048*196*2 threads
    int cell = idx >> 1, half = idx & 1;
    int b = cell / 196, p = cell % 196;
    int oy = p / 14, ox = p % 14;
    const uint32_t* h = g_h1 + b * 784;

    int rbase = 2 * oy - 1, cbase = 2 * ox - 1;
    bool rv0 = oy > 0, rv3 = oy < 13, cv0 = ox > 0, cv3 = ox < 13;

    uint32_t win[16], msk[16];
#pragma unroll
    for (int i = 0; i < 4; i++) {
        bool rok = (i == 0) ? rv0 : (i == 3 ? rv3 : true);
#pragma unroll
        for (int j = 0; j < 4; j++) {
            bool cok = (j == 0) ? cv0 : (j == 3 ? cv3 : true);
            bool v = rok && cok;
            msk[i * 4 + j] = v ? 0xFFFFFFFFu : 0u;
            win[i * 4 + j] = v ? h[(rbase + i) * 28 + (cbase + j)] : 0u;
        }
    }
    int vr0 = rv0 ? 3 : 2, vr1 = rv3 ? 3 : 2;
    int vc0 = cv0 ? 3 : 2, vc1 = cv3 ? 3 : 2;
    int base0 = 32 * vr0 * vc0, base1 = 32 * vr0 * vc1;
    int base2 = 32 * vr1 * vc0, base3 = 32 * vr1 * vc1;

    int cb = half * 32;
    uint32_t obits = 0;
    for (int ci = 0; ci < 32; ci++) {
        const uint4* wp = (const uint4*)(swt + (cb + ci) * 12);
        uint4 wa = wp[0], wb = wp[1], wc = wp[2];
        uint32_t wt[9] = {wa.x, wa.y, wa.z, wa.w, wb.x, wb.y, wb.z, wb.w, wc.x};
        int a0 = 0, a1 = 0, a2 = 0, a3 = 0;
#pragma unroll
        for (int dy = 0; dy < 3; dy++)
#pragma unroll
            for (int dx = 0; dx < 3; dx++) {
                uint32_t w = wt[dy * 3 + dx];
                int i0 = dy * 4 + dx;
                a0 += __popc((win[i0] ^ w) & msk[i0]);
                a1 += __popc((win[i0 + 1] ^ w) & msk[i0 + 1]);
                a2 += __popc((win[i0 + 4] ^ w) & msk[i0 + 4]);
                a3 += __popc((win[i0 + 5] ^ w) & msk[i0 + 5]);
            }
        int d0 = base0 - 2 * a0, d1 = base1 - 2 * a1;
        int d2 = base2 - 2 * a2, d3 = base3 - 2 * a3;
        int dmax = max(max(d0, d1), max(d2, d3));
        int dmin = min(min(d0, d1), min(d2, d3));
        float4 bn = sbn[cb + ci];
        int ds = (bn.x >= 0.f) ? dmax : dmin;       // BN monotone in dot -> exact
        float val = ((float)ds - bn.y) * bn.x + bn.z;
        obits |= (uint32_t)(val >= 0.f) << ci;
    }
    ((uint32_t*)g_h2)[cell * 2 + half] = obits;
}

// ---------------- block2: binary conv(64->64) + BN + pool + sign, 32 ch/thread ----------------
__global__ void __launch_bounds__(256) conv3_kernel() {
    __shared__ __align__(16) unsigned long long swt[640];
    __shared__ float4 sbn[64];
    int t = threadIdx.x;
    for (int i = t; i < 640; i += 256) swt[i] = g_w3p[i];
    if (t < 64) sbn[t] = g_bn3[t];
    __syncthreads();

    int idx = blockIdx.x * 256 + t;                 // 2048*49*2 threads
    int cell = idx >> 1, half = idx & 1;
    int b = cell / 49, p = cell % 49;
    int oy = p / 7, ox = p % 7;
    const unsigned long long* h = g_h2 + b * 196;

    int rbase = 2 * oy - 1, cbase = 2 * ox - 1;
    bool rv0 = oy > 0, rv3 = oy < 6, cv0 = ox > 0, cv3 = ox < 6;

    unsigned long long win[16], msk[16];
#pragma unroll
    for (int i = 0; i < 4; i++) {
        bool rok = (i == 0) ? rv0 : (i == 3 ? rv3 : true);
#pragma unroll
        for (int j = 0; j < 4; j++) {
            bool cok = (j == 0) ? cv0 : (j == 3 ? cv3 : true);
            bool v = rok && cok;
            msk[i * 4 + j] = v ? ~0ull : 0ull;
            win[i * 4 + j] = v ? h[(rbase + i) * 14 + (cbase + j)] : 0ull;
        }
    }
    int vr0 = rv0 ? 3 : 2, vr1 = rv3 ? 3 : 2;
    int vc0 = cv0 ? 3 : 2, vc1 = cv3 ? 3 : 2;
    int base0 = 64 * vr0 * vc0, base1 = 64 * vr0 * vc1;
    int base2 = 64 * vr1 * vc0, base3 = 64 * vr1 * vc1;

    int cb = half * 32;
    uint32_t obits = 0;
    for (int ci = 0; ci < 32; ci++) {
        const ulonglong2* wp = (const ulonglong2*)(swt + (cb + ci) * 10);
        ulonglong2 p0 = wp[0], p1 = wp[1], p2 = wp[2], p3 = wp[3], p4 = wp[4];
        unsigned long long wt[9] = {p0.x, p0.y, p1.x, p1.y, p2.x, p2.y, p3.x, p3.y, p4.x};
        int a0 = 0, a1 = 0, a2 = 0, a3 = 0;
#pragma unroll
        for (int dy = 0; dy < 3; dy++)
#pragma unroll
            for (int dx = 0; dx < 3; dx++) {
                unsigned long long w = wt[dy * 3 + dx];
                int i0 = dy * 4 + dx;
                a0 += __popcll((win[i0] ^ w) & msk[i0]);
                a1 += __popcll((win[i0 + 1] ^ w) & msk[i0 + 1]);
                a2 += __popcll((win[i0 + 4] ^ w) & msk[i0 + 4]);
                a3 += __popcll((win[i0 + 5] ^ w) & msk[i0 + 5]);
            }
        int d0 = base0 - 2 * a0, d1 = base1 - 2 * a1;
        int d2 = base2 - 2 * a2, d3 = base3 - 2 * a3;
        int dmax = max(max(d0, d1), max(d2, d3));
        int dmin = min(min(d0, d1), min(d2, d3));
        float4 bn = sbn[cb + ci];
        int ds = (bn.x >= 0.f) ? dmax : dmin;
        float val = ((float)ds - bn.y) * bn.x + bn.z;
        obits |= (uint32_t)(val >= 0.f) << ci;
    }
    g_h3u[cell * 2 + half] = obits;
}

// ---------------- classifier ----------------
__global__ void __launch_bounds__(256) fc_kernel(const float* __restrict__ w_head,
                                                 const float* __restrict__ b_head,
                                                 float* __restrict__ out) {
    __shared__ unsigned long long xrow[49];
    __shared__ float h4[256];
    int b = blockIdx.x, t = threadIdx.x;
    if (t < 49) {
        uint32_t lo = g_h3u[(b * 49 + t) * 2];
        uint32_t hi = g_h3u[(b * 49 + t) * 2 + 1];
        xrow[t] = (unsigned long long)lo | ((unsigned long long)hi << 32);
    }
    __syncthreads();

    const unsigned long long* wr = g_wfcp + t * 49;
    int acc = 0;
#pragma unroll
    for (int p = 0; p < 49; p++) acc += __popcll(xrow[p] ^ wr[p]);
    float4 bn = g_bn4[t];
    h4[t] = ((float)(3136 - 2 * acc) - bn.y) * bn.x + bn.z;
    __syncthreads();

    if (t < 10) {
        float s = b_head[t];
        const float* wh = w_head + t * 256;
#pragma unroll 8
        for (int c = 0; c < 256; c++) s += h4[c] * wh[c];
        out[b * 10 + t] = s;
    }
}

// ---------------- launch ----------------
extern "C" void kernel_launch(void* const* d_in, const int* in_sizes, int n_in,
                              void* d_out, int out_size) {
    const float* x      = (const float*)d_in[0];
    const float* w_stem = (const float*)d_in[1];
    const float* g1 = (const float*)d_in[2];
    const float* b1 = (const float*)d_in[3];
    const float* m1 = (const float*)d_in[4];
    const float* v1 = (const float*)d_in[5];
    const float* w2 = (const float*)d_in[6];
    const float* g2 = (const float*)d_in[7];
    const float* b2 = (const float*)d_in[8];
    const float* m2 = (const float*)d_in[9];
    const float* v2 = (const float*)d_in[10];
    const float* w3 = (const float*)d_in[11];
    const float* g3 = (const float*)d_in[12];
    const float* b3 = (const float*)d_in[13];
    const float* m3 = (const float*)d_in[14];
    const float* v3 = (const float*)d_in[15];
    const float* w_fc = (const float*)d_in[16];
    const float* g4 = (const float*)d_in[17];
    const float* b4 = (const float*)d_in[18];
    const float* m4 = (const float*)d_in[19];
    const float* v4 = (const float*)d_in[20];
    const float* w_head = (const float*)d_in[21];
    const float* b_head = (const float*)d_in[22];
    float* out = (float*)d_out;

    pack_kernel<<<57, 256>>>(w2, w3, w_fc, g1, v1, m1, b1, g2, v2, m2, b2,
                             g3, v3, m3, b3, g4, v4, m4, b4);
    stem_kernel<<<(BATCH * 784 * 2) / 256, 256>>>(x, w_stem);
    conv2_kernel<<<(BATCH * 196 * 2) / 256, 256>>>();
    conv3_kernel<<<(BATCH * 49 * 2) / 256, 256>>>();
    fc_kernel<<<BATCH, 256>>>(w_head, b_head, out);
}